// round 14
// baseline (speedup 1.0000x reference)
#include <cuda_runtime.h>
#include <cuda_fp16.h>
#include <cstddef>

#define NB     2
#define N_IN   163842
#define N_OUT  40962
#define CDIM   128
#define KCAND  7

// Scratch (static device globals — no runtime allocation).
// Pooled weighted sums accumulate directly in fp16 (atomic f16x2 reductions).
__device__ __half g_down_h[(size_t)NB * N_OUT * CDIM];   // 21 MB
__device__ float  g_denom[N_OUT];

// ---------------------------------------------------------------------------
// Kernel 0: zero fp16 scratch + denom. Fat grid-resident blocks: 1184 CTAs
// (8 per SM), 256 threads, 4x uint4 (64B) per thread per iteration, 32-bit
// index arithmetic. Profile showed the old 5121-tiny-CTA version was
// CTA-overhead/issue bound (issue=76%, all mem pipes <28%).
// ---------------------------------------------------------------------------
#define ZBLOCKS 1184
__global__ void __launch_bounds__(256) zero_kernel() {
    const unsigned total16 = (unsigned)((size_t)NB * N_OUT * CDIM *
                                        sizeof(__half) / 16);  // 1,310,784
    const unsigned nthr    = ZBLOCKS * 256;                    // 303,104
    unsigned t = blockIdx.x * 256u + threadIdx.x;

    uint4 z; z.x = 0u; z.y = 0u; z.z = 0u; z.w = 0u;
    uint4* base = reinterpret_cast<uint4*>(g_down_h);

    // 1,310,784 / 4 = 327,696 groups of 4; stride the grid over groups.
    for (unsigned g = t; g * 4u + 3u < total16; g += nthr) {
        uint4* p = base + g * 4u;
        p[0] = z; p[1] = z; p[2] = z; p[3] = z;
    }
    // Tail (total16 % 4 == 0 here, but keep exact): handled above since
    // 1,310,784 = 327,696 * 4 exactly.

    if (t < N_OUT) g_denom[t] = 0.f;
    else {
        for (unsigned d = t; d < N_OUT; d += nthr) g_denom[d] = 0.f;
    }
}

// ---------------------------------------------------------------------------
// Kernel 1: scatter-add in fp16 (best-measured form, unchanged):
//   down_h[b, parent[n], :] += fp16(omega[n] * x[b, n, :])
//   denom[parent[n]]        += omega[n]
// One warp per input row n; lanes 0-15 -> b=0, lanes 16-31 -> b=1; each lane
// covers 8 channels: 2x LDG.128 + pack + red.global.add.noftz.v4.f16x2.
// ---------------------------------------------------------------------------
__global__ void __launch_bounds__(256) scatter_kernel(
        const float* __restrict__ x,
        const float* __restrict__ omega,
        const int*   __restrict__ parent) {
    const int warp = (int)(((size_t)blockIdx.x * blockDim.x + threadIdx.x) >> 5);
    const int lane = threadIdx.x & 31;
    if (warp >= N_IN) return;

    const int   p  = parent[warp];   // broadcast
    const float om = omega[warp];    // broadcast

    const int sub = lane >> 4;       // batch
    const int li  = lane & 15;       // 16B slot (8 channels) within the row

    const float4* xr =
        reinterpret_cast<const float4*>(x + ((size_t)sub * N_IN + warp) * CDIM)
        + li * 2;
    float4 a = xr[0];
    float4 b = xr[1];
    a.x *= om; a.y *= om; a.z *= om; a.w *= om;
    b.x *= om; b.y *= om; b.z *= om; b.w *= om;

    __half2 h0 = __floats2half2_rn(a.x, a.y);
    __half2 h1 = __floats2half2_rn(a.z, a.w);
    __half2 h2 = __floats2half2_rn(b.x, b.y);
    __half2 h3 = __floats2half2_rn(b.z, b.w);

    __half* dst = g_down_h + ((size_t)sub * N_OUT + p) * CDIM + li * 8;
    asm volatile("red.global.add.noftz.v4.f16x2 [%0], {%1, %2, %3, %4};"
                 :: "l"(dst),
                    "r"(*reinterpret_cast<unsigned*>(&h0)),
                    "r"(*reinterpret_cast<unsigned*>(&h1)),
                    "r"(*reinterpret_cast<unsigned*>(&h2)),
                    "r"(*reinterpret_cast<unsigned*>(&h3))
                 : "memory");

    if (lane == 0) {
        atomicAdd(&g_denom[p], om);
    }
}

// ---------------------------------------------------------------------------
// Kernel 2: gather (best-measured R8/R12 form — at its L1tex wavefront
// floor: ~28 read wf + 8 store wf + 4 weight wf per warp, all 128B-dense).
// Weights lane-parallel (lanes 0-6: 3 scalar LDG + 1 MUFU each), width-8
// butterfly, denom folded, clamp, pack to half2. Accumulation: lanes 0-15 ->
// b=0, 16-31 -> b=1; per k: 2 SHFL + 1 LDG.128 + 4 HFMA2 into dual
// interleaved fp16 partials (chains <= 4), f32 finalize + 2x STG.128.
// ---------------------------------------------------------------------------
__global__ void __launch_bounds__(256) gather_kernel(
        const float* __restrict__ delta,
        const float* __restrict__ mask,
        const int*   __restrict__ cand,
        float*       __restrict__ out) {
    const int warp = (int)(((size_t)blockIdx.x * blockDim.x + threadIdx.x) >> 5);
    const int lane = threadIdx.x & 31;
    if (warp >= N_IN) return;

    const float INV2S2 = 3.125f;  // 1 / (2 * 0.4^2)

    // ---- lanes 0-6: per-candidate weight ----
    float w = 0.f;
    int   c = 0;
    if (lane < KCAND) {
        const size_t o = (size_t)warp * KCAND + lane;
        const float d = delta[o];
        const float m = mask[o];
        c = cand[o];
        w = __expf(-d * d * INV2S2) * m;
    }
    // sum over lanes 0-7 (lane 7 contributes 0), width-8 butterfly
    float s = w;
    s += __shfl_down_sync(0xffffffffu, s, 4, 8);
    s += __shfl_down_sync(0xffffffffu, s, 2, 8);
    s += __shfl_down_sync(0xffffffffu, s, 1, 8);
    s  = __shfl_sync(0xffffffffu, s, 0, 8);   // lanes 0-7 get total

    unsigned whbits = 0;
    if (lane < KCAND) {
        const float den = fmaxf(__ldg(&g_denom[c]), 1e-8f);
        float wf = w / (fmaxf(s, 1e-8f) * den);
        // Clamp: zero-parent outputs give wf ~ 1e8 -> fp16 inf -> inf*0 NaN.
        // Their rows are all-zero, so any finite weight is exact.
        wf = fminf(wf, 1000.0f);
        const __half2 wh = __float2half2_rn(wf);
        whbits = *reinterpret_cast<const unsigned*>(&wh);
    }

    // ---- row accumulation (fp16 HFMA2, two interleaved partials) ----
    const int sub = lane >> 4;
    const int li  = lane & 15;

    const __half2 hz = __float2half2_rn(0.f);
    __half2 accA[4] = {hz, hz, hz, hz};
    __half2 accB[4] = {hz, hz, hz, hz};

#pragma unroll
    for (int k = 0; k < KCAND; ++k) {
        const unsigned wb = __shfl_sync(0xffffffffu, whbits, k);
        const int      ik = __shfl_sync(0xffffffffu, c, k);
        const __half2  wh = *reinterpret_cast<const __half2*>(&wb);
        const float4 raw = __ldg(reinterpret_cast<const float4*>(
            g_down_h + ((size_t)sub * N_OUT + ik) * CDIM) + li);
        const __half2* h2 = reinterpret_cast<const __half2*>(&raw);
        if ((k & 1) == 0) {
#pragma unroll
            for (int j = 0; j < 4; ++j) accA[j] = __hfma2(h2[j], wh, accA[j]);
        } else {
#pragma unroll
            for (int j = 0; j < 4; ++j) accB[j] = __hfma2(h2[j], wh, accB[j]);
        }
    }

    // Finalize in f32: convert both partials, add, store.
    float res[8];
#pragma unroll
    for (int j = 0; j < 4; ++j) {
        const float2 a = __half22float2(accA[j]);
        const float2 b = __half22float2(accB[j]);
        res[2 * j]     = a.x + b.x;
        res[2 * j + 1] = a.y + b.y;
    }

    float* dst = out + ((size_t)sub * N_IN + warp) * CDIM + li * 8;
    reinterpret_cast<float4*>(dst)[0] = make_float4(res[0], res[1], res[2], res[3]);
    reinterpret_cast<float4*>(dst)[1] = make_float4(res[4], res[5], res[6], res[7]);
}

// ---------------------------------------------------------------------------
// Launcher. Input order: x, omega, delta, cand_mask, parent_idx, cand_idx.
// Output: float32 (B, N_IN, C). Single stream.
// ---------------------------------------------------------------------------
extern "C" void kernel_launch(void* const* d_in, const int* in_sizes, int n_in,
                              void* d_out, int out_size) {
    const float* x      = (const float*)d_in[0];
    const float* omega  = (const float*)d_in[1];
    const float* delta  = (const float*)d_in[2];
    const float* mask   = (const float*)d_in[3];
    const int*   parent = (const int*)d_in[4];
    const int*   cand   = (const int*)d_in[5];
    float*       out    = (float*)d_out;

    (void)in_sizes; (void)n_in; (void)out_size;

    // Zero fp16 scratch + denom: 8 resident CTAs per SM, 64B/thread/iter.
    zero_kernel<<<ZBLOCKS, 256>>>();

    // Scatter pool (fp16 vector reductions)
    {
        const int threads = 256;  // 8 warps / block
        const int blocks  = (N_IN + 8 - 1) / 8;
        scatter_kernel<<<blocks, threads>>>(x, omega, parent);
    }
    // Gather + weight (fp16 HFMA2 accumulate, f32 finalize)
    {
        const int threads = 256;
        const int blocks  = (N_IN + 8 - 1) / 8;
        gather_kernel<<<blocks, threads>>>(delta, mask, cand, out);
    }
}

// round 15
// speedup vs baseline: 1.0638x; 1.0638x over previous
#include <cuda_runtime.h>
#include <cuda_fp16.h>
#include <cstddef>

#define NB     2
#define N_IN   163842
#define N_OUT  40962
#define CDIM   128
#define KCAND  7

// ---------------------------------------------------------------------------
// Unified scratch buffer (single __device__ global; no runtime allocation).
// Layout:
//   [0,            163,848)   g_denom   (N_OUT f32)
//   [167,936,   21,140,480)   g_down_h  (NB*N_OUT*CDIM fp16), 4KB-aligned
//   padded to 21,143,552 B = 5162 blocks x 256 threads x 16 B  (exact grid)
// One uint4 fill covers both regions (f32 0.0 and fp16 0.0 are bit-zero).
// ---------------------------------------------------------------------------
#define DOWN_OFF   167936u
#define ZERO_BLKS  5162
__device__ uint4 g_scratch[(size_t)ZERO_BLKS * 256];

__device__ __forceinline__ float* denom_ptr() {
    return reinterpret_cast<float*>(g_scratch);
}
__device__ __forceinline__ __half* down_ptr() {
    return reinterpret_cast<__half*>(
        reinterpret_cast<char*>(g_scratch) + DOWN_OFF);
}

// ---------------------------------------------------------------------------
// Kernel 0: zero the scratch. Exact grid: one STG.128 per thread, no loop,
// no bounds check, 32-bit indexing (~6 instrs/thread vs ~14 before — the
// 7.1us version was issue-bound on overhead instructions at issue=76%).
// ---------------------------------------------------------------------------
__global__ void __launch_bounds__(256) zero_kernel() {
    const unsigned t = blockIdx.x * 256u + threadIdx.x;
    uint4 z; z.x = 0u; z.y = 0u; z.z = 0u; z.w = 0u;
    g_scratch[t] = z;
}

// ---------------------------------------------------------------------------
// Kernel 1: scatter-add in fp16 (R8 form, at the HBM-read floor):
//   down[b, parent[n], :] += fp16(omega[n] * x[b, n, :])
//   denom[parent[n]]      += omega[n]
// One warp per input row n; lanes 0-15 -> b=0, lanes 16-31 -> b=1; each lane
// covers 8 channels: 2x LDG.128 + pack + red.global.add.noftz.v4.f16x2.
// ---------------------------------------------------------------------------
__global__ void __launch_bounds__(256) scatter_kernel(
        const float* __restrict__ x,
        const float* __restrict__ omega,
        const int*   __restrict__ parent) {
    const int warp = (int)(((size_t)blockIdx.x * blockDim.x + threadIdx.x) >> 5);
    const int lane = threadIdx.x & 31;
    if (warp >= N_IN) return;

    const int   p  = parent[warp];   // broadcast
    const float om = omega[warp];    // broadcast

    const int sub = lane >> 4;       // batch
    const int li  = lane & 15;       // 16B slot (8 channels) within the row

    const float4* xr =
        reinterpret_cast<const float4*>(x + ((size_t)sub * N_IN + warp) * CDIM)
        + li * 2;
    float4 a = xr[0];
    float4 b = xr[1];
    a.x *= om; a.y *= om; a.z *= om; a.w *= om;
    b.x *= om; b.y *= om; b.z *= om; b.w *= om;

    __half2 h0 = __floats2half2_rn(a.x, a.y);
    __half2 h1 = __floats2half2_rn(a.z, a.w);
    __half2 h2 = __floats2half2_rn(b.x, b.y);
    __half2 h3 = __floats2half2_rn(b.z, b.w);

    __half* dst = down_ptr() + ((size_t)sub * N_OUT + p) * CDIM + li * 8;
    asm volatile("red.global.add.noftz.v4.f16x2 [%0], {%1, %2, %3, %4};"
                 :: "l"(dst),
                    "r"(*reinterpret_cast<unsigned*>(&h0)),
                    "r"(*reinterpret_cast<unsigned*>(&h1)),
                    "r"(*reinterpret_cast<unsigned*>(&h2)),
                    "r"(*reinterpret_cast<unsigned*>(&h3))
                 : "memory");

    if (lane == 0) {
        atomicAdd(&denom_ptr()[p], om);
    }
}

// ---------------------------------------------------------------------------
// Kernel 2: gather (R8 form — at the LTS byte floor: 755MB through L2
// = ~120k cyc = the measured duration). One warp per row n.
// Weights lane-parallel (lanes 0-6: 3 scalar LDG + 1 MUFU each), width-8
// butterfly, denom folded, clamp, pack to half2. Accumulation: lanes 0-15 ->
// b=0, 16-31 -> b=1; per k: 2 SHFL + 1 LDG.128 + 4 HFMA2 into dual
// interleaved fp16 partials (chains <= 4), f32 finalize + 2x STG.128.
// ---------------------------------------------------------------------------
__global__ void __launch_bounds__(256) gather_kernel(
        const float* __restrict__ delta,
        const float* __restrict__ mask,
        const int*   __restrict__ cand,
        float*       __restrict__ out) {
    const int warp = (int)(((size_t)blockIdx.x * blockDim.x + threadIdx.x) >> 5);
    const int lane = threadIdx.x & 31;
    if (warp >= N_IN) return;

    const float INV2S2 = 3.125f;  // 1 / (2 * 0.4^2)

    // ---- lanes 0-6: per-candidate weight ----
    float w = 0.f;
    int   c = 0;
    if (lane < KCAND) {
        const size_t o = (size_t)warp * KCAND + lane;
        const float d = delta[o];
        const float m = mask[o];
        c = cand[o];
        w = __expf(-d * d * INV2S2) * m;
    }
    // sum over lanes 0-7 (lane 7 contributes 0), width-8 butterfly
    float s = w;
    s += __shfl_down_sync(0xffffffffu, s, 4, 8);
    s += __shfl_down_sync(0xffffffffu, s, 2, 8);
    s += __shfl_down_sync(0xffffffffu, s, 1, 8);
    s  = __shfl_sync(0xffffffffu, s, 0, 8);   // lanes 0-7 get total

    unsigned whbits = 0;
    if (lane < KCAND) {
        const float den = fmaxf(__ldg(&denom_ptr()[c]), 1e-8f);
        float wf = w / (fmaxf(s, 1e-8f) * den);
        // Clamp: zero-parent outputs give wf ~ 1e8 -> fp16 inf -> inf*0 NaN.
        // Their rows are all-zero, so any finite weight is exact.
        wf = fminf(wf, 1000.0f);
        const __half2 wh = __float2half2_rn(wf);
        whbits = *reinterpret_cast<const unsigned*>(&wh);
    }

    // ---- row accumulation (fp16 HFMA2, two interleaved partials) ----
    const int sub = lane >> 4;
    const int li  = lane & 15;

    const __half2 hz = __float2half2_rn(0.f);
    __half2 accA[4] = {hz, hz, hz, hz};
    __half2 accB[4] = {hz, hz, hz, hz};

#pragma unroll
    for (int k = 0; k < KCAND; ++k) {
        const unsigned wb = __shfl_sync(0xffffffffu, whbits, k);
        const int      ik = __shfl_sync(0xffffffffu, c, k);
        const __half2  wh = *reinterpret_cast<const __half2*>(&wb);
        const float4 raw = __ldg(reinterpret_cast<const float4*>(
            down_ptr() + ((size_t)sub * N_OUT + ik) * CDIM) + li);
        const __half2* h2 = reinterpret_cast<const __half2*>(&raw);
        if ((k & 1) == 0) {
#pragma unroll
            for (int j = 0; j < 4; ++j) accA[j] = __hfma2(h2[j], wh, accA[j]);
        } else {
#pragma unroll
            for (int j = 0; j < 4; ++j) accB[j] = __hfma2(h2[j], wh, accB[j]);
        }
    }

    // Finalize in f32: convert both partials, add, store.
    float res[8];
#pragma unroll
    for (int j = 0; j < 4; ++j) {
        const float2 a = __half22float2(accA[j]);
        const float2 b = __half22float2(accB[j]);
        res[2 * j]     = a.x + b.x;
        res[2 * j + 1] = a.y + b.y;
    }

    float* dst = out + ((size_t)sub * N_IN + warp) * CDIM + li * 8;
    reinterpret_cast<float4*>(dst)[0] = make_float4(res[0], res[1], res[2], res[3]);
    reinterpret_cast<float4*>(dst)[1] = make_float4(res[4], res[5], res[6], res[7]);
}

// ---------------------------------------------------------------------------
// Launcher. Input order: x, omega, delta, cand_mask, parent_idx, cand_idx.
// Output: float32 (B, N_IN, C). Single stream.
// ---------------------------------------------------------------------------
extern "C" void kernel_launch(void* const* d_in, const int* in_sizes, int n_in,
                              void* d_out, int out_size) {
    const float* x      = (const float*)d_in[0];
    const float* omega  = (const float*)d_in[1];
    const float* delta  = (const float*)d_in[2];
    const float* mask   = (const float*)d_in[3];
    const int*   parent = (const int*)d_in[4];
    const int*   cand   = (const int*)d_in[5];
    float*       out    = (float*)d_out;

    (void)in_sizes; (void)n_in; (void)out_size;

    // Zero scratch: exact grid, one STG.128 per thread.
    zero_kernel<<<ZERO_BLKS, 256>>>();

    // Scatter pool (fp16 vector reductions)
    {
        const int threads = 256;  // 8 warps / block
        const int blocks  = (N_IN + 8 - 1) / 8;
        scatter_kernel<<<blocks, threads>>>(x, omega, parent);
    }
    // Gather + weight (fp16 HFMA2 accumulate, f32 finalize)
    {
        const int threads = 256;
        const int blocks  = (N_IN + 8 - 1) / 8;
        gather_kernel<<<blocks, threads>>>(delta, mask, cand, out);
    }
}